// round 6
// baseline (speedup 1.0000x reference)
#include <cuda_runtime.h>
#include <cuda_bf16.h>
#include <cub/cub.cuh>
#include <cstdint>

typedef unsigned int u32;
typedef unsigned long long u64;

// Problem constants
constexpr int Bq = 2, Eq = 16, Hq = 160, Wq = 288, Nq = 12, Tq = 2;
constexpr int HW  = Hq * Wq;            // 46080
constexpr int P   = Tq * HW;            // 92160 pixels per instance
constexpr int BN  = Bq * Nq;            // 24 instances

constexpr int CH   = 36;                // chunks per (b,t)
constexpr int CPIX = 1280;              // pixels per chunk (HW = 36*1280)
constexpr int STB  = Bq * Tq * CH;      // 144 tile blocks
constexpr int NCHK = Tq * CH;           // 72 partial chunks per instance

constexpr int NB  = 1024;               // histogram bins over err in [0,2]
constexpr float FXS = 4096.0f;          // fixed-point scale 2^12
// global/smem hist packing: (pos<<47) | (neg<<30) | fxsum
//   pos,neg <= 92160 < 2^17; fxsum <= 92160*2*4096 = 7.6e8 < 2^30

constexpr int LCH = 8;                  // loss chunks per instance
constexpr int LBINS = NB / LCH;         // 128
constexpr int LTH = 128;

// -------- scratch (static device globals; no runtime allocation) --------
__device__ float g_part[BN * NCHK * 33];
__device__ float g_w2[BN * Eq];         // var
__device__ float g_w1[BN * Eq];         // -2*var*mean
__device__ float g_c[BN];               // sum var*mean^2
__device__ float g_cnt[BN];
__device__ u64 g_hist[BN * NB];
__device__ float g_losspart[BN * LCH];
__device__ int g_done = 0;

// -------- kernel 1: stats via smem feat tile, instance-outer loop --------
__global__ void __launch_bounds__(256, 1) k_stats(
    const float* __restrict__ f1, const float* __restrict__ f2,
    const int* __restrict__ gt) {
    extern __shared__ float tile[];     // [Eq][CPIX] = 80KB
    __shared__ float ws[8][33];

    int blk = blockIdx.x;
    int b = blk / (Tq * CH);
    int r = blk % (Tq * CH);
    int t = r / CH, ch = r % CH;
    int hw0 = ch * CPIX;
    const float* fb = (t ? f2 : f1) + (size_t)b * Eq * HW + hw0;

    for (int k = threadIdx.x; k < Eq * CPIX; k += 256) {
        int e = k / CPIX, i = k - e * CPIX;
        tile[e * CPIX + i] = fb[(size_t)e * HW + i];
    }
    __syncthreads();

    int warp = threadIdx.x >> 5, lane = threadIdx.x & 31;

    for (int n = 0; n < Nq; n++) {
        int bn = b * Nq + n;
        const int* gtp = gt + ((size_t)bn * Tq + t) * HW + hw0;

        float a[33];
#pragma unroll
        for (int q = 0; q < 33; q++) a[q] = 0.f;

#pragma unroll
        for (int it = 0; it < CPIX / 256; it++) {
            int i = it * 256 + threadIdx.x;
            float m = (float)gtp[i];
            a[32] += m;
#pragma unroll
            for (int e = 0; e < Eq; e++) {
                float v = tile[e * CPIX + i];
                float mv = m * v;
                a[e] += mv;
                a[16 + e] = fmaf(mv, v, a[16 + e]);
            }
        }

#pragma unroll
        for (int q = 0; q < 33; q++)
#pragma unroll
            for (int off = 16; off > 0; off >>= 1)
                a[q] += __shfl_down_sync(0xFFFFFFFFu, a[q], off);

        if (lane == 0)
#pragma unroll
            for (int q = 0; q < 33; q++) ws[warp][q] = a[q];
        __syncthreads();

        if (threadIdx.x < 33) {
            float s = 0.f;
#pragma unroll
            for (int w = 0; w < 8; w++) s += ws[w][threadIdx.x];
            g_part[((size_t)bn * NCHK + (t * CH + ch)) * 33 + threadIdx.x] = s;
        }
        __syncthreads();
    }
}

// -------- kernel 2: finalize -> w2 (var), w1 (-2*var*mean), c, cnt --------
__global__ void k_stats2() {
    int bn = blockIdx.x;
    __shared__ float sums[33];
    __shared__ float vm2[16];
    int tid = threadIdx.x;
    if (tid < 33) {
        float s = 0.f;
        for (int c = 0; c < NCHK; c++)
            s += g_part[((size_t)bn * NCHK + c) * 33 + tid];
        sums[tid] = s;
    }
    __syncthreads();
    float cnt = sums[32];
    if (tid < Eq) {
        float mean = sums[tid] / cnt;
        float var  = (sums[16 + tid] - cnt * mean * mean) / (cnt - 1.0f);
        g_w2[bn * Eq + tid] = var;
        g_w1[bn * Eq + tid] = -2.0f * var * mean;
        vm2[tid] = var * mean * mean;
    }
    __syncthreads();
    if (tid == 0) {
        float c = 0.f;
#pragma unroll
        for (int e = 0; e < Eq; e++) c += vm2[e];
        g_c[bn] = c;
        g_cnt[bn] = cnt;
    }
}

// -------- kernel 3: fused error + histogram, tiled, instance-outer --------
// dynamic smem: u64 hist[Nq*NB] (96KB) then float tile[Eq*CPIX] (80KB)
__global__ void __launch_bounds__(256, 1) k_errhist(
    const float* __restrict__ f1, const float* __restrict__ f2,
    const int* __restrict__ gt) {
    extern __shared__ u64 sh[];
    u64* hist = sh;
    float* tile = (float*)(sh + Nq * NB);

    int blk = blockIdx.x;
    int b = blk / (Tq * CH);
    int r = blk % (Tq * CH);
    int t = r / CH, ch = r % CH;
    int hw0 = ch * CPIX;
    const float* fb = (t ? f2 : f1) + (size_t)b * Eq * HW + hw0;

    for (int i = threadIdx.x; i < Nq * NB; i += 256) hist[i] = 0ull;
    for (int k = threadIdx.x; k < Eq * CPIX; k += 256) {
        int e = k / CPIX, i = k - e * CPIX;
        tile[e * CPIX + i] = fb[(size_t)e * HW + i];
    }
    __syncthreads();

    int lane = threadIdx.x & 31;

    for (int n = 0; n < Nq; n++) {
        int bn = b * Nq + n;
        float w2[Eq], w1[Eq];
#pragma unroll
        for (int e = 0; e < Eq; e++) {
            w2[e] = g_w2[bn * Eq + e];
            w1[e] = g_w1[bn * Eq + e];
        }
        float cc = g_c[bn];
        const int* gtp = gt + ((size_t)bn * Tq + t) * HW + hw0;

        u32 c0 = 0, cM = 0, s0 = 0, sM = 0;   // edge bins: pos<<16|neg packed

#pragma unroll
        for (int it = 0; it < CPIX / 256; it++) {
            int i = it * 256 + threadIdx.x;
            int m = gtp[i];
            float d = cc;
#pragma unroll
            for (int e = 0; e < Eq; e++) {
                float v = tile[e * CPIX + i];
                d = fmaf(v, fmaf(v, w2[e], w1[e]), d);
            }
            float logit = 2.0f * __expf(-0.5f * d) - 1.0f;
            float err = m ? (1.0f - logit) : (1.0f + logit);
            u32 fx = (u32)(err * FXS + 0.5f);
            int bin = (int)(err * (0.5f * NB));
            if (bin > NB - 1) bin = NB - 1;
            u32 pc = m ? 0x10000u : 1u;
            if (bin == 0)           { c0 += pc; s0 += fx; }
            else if (bin == NB - 1) { cM += pc; sM += fx; }
            else {
                u64 add = (m ? (1ull << 47) : (1ull << 30)) | (u64)fx;
                atomicAdd(&hist[n * NB + bin], add);
            }
        }
        // warp-reduce edge accumulators, flush to global once per warp
#pragma unroll
        for (int off = 16; off > 0; off >>= 1) {
            c0 += __shfl_down_sync(0xFFFFFFFFu, c0, off);
            cM += __shfl_down_sync(0xFFFFFFFFu, cM, off);
            s0 += __shfl_down_sync(0xFFFFFFFFu, s0, off);
            sM += __shfl_down_sync(0xFFFFFFFFu, sM, off);
        }
        if (lane == 0) {
            size_t gb = (size_t)bn * NB;
            if (c0)
                atomicAdd(&g_hist[gb + 0],
                    ((u64)(c0 >> 16) << 47) | ((u64)(c0 & 0xFFFFu) << 30) | (u64)s0);
            if (cM)
                atomicAdd(&g_hist[gb + NB - 1],
                    ((u64)(cM >> 16) << 47) | ((u64)(cM & 0xFFFFu) << 30) | (u64)sM);
        }
    }
    __syncthreads();

    // merge block-local mid bins into global (same packing, direct add)
    size_t gb0 = (size_t)b * Nq * NB;
    for (int k = threadIdx.x; k < Nq * NB; k += 256) {
        u64 h = hist[k];
        if (h) atomicAdd(&g_hist[gb0 + k], h);
    }
}

// -------- kernel 4: Lovász descending-bin scan + fused final reduce --------
__global__ void k_losshist(float* __restrict__ out) {
    int bn = blockIdx.x / LCH;
    int ch = blockIdx.x % LCH;
    float gts = g_cnt[bn];
    size_t gbase = (size_t)bn * NB;

    typedef cub::BlockScan<u64, LTH> Scan;
    __shared__ typename Scan::TempStorage ts;
    __shared__ u64 wred[4];
    __shared__ u64 s_prefix;

    // prefix: reduce (pos, tot) over descending positions before this chunk
    u64 acc = 0ull;                     // (pos<<32)|tot
    for (int i = NB - ch * LBINS + (int)threadIdx.x; i < NB; i += LTH) {
        u64 h = g_hist[gbase + i];
        u32 pos = (u32)(h >> 47);
        u32 neg = (u32)(h >> 30) & 0x1FFFFu;
        acc += ((u64)pos << 32) | (u64)(pos + neg);
    }
#pragma unroll
    for (int off = 16; off > 0; off >>= 1)
        acc += __shfl_down_sync(0xFFFFFFFFu, acc, off);
    int warp = threadIdx.x >> 5, lane = threadIdx.x & 31;
    if (lane == 0) wred[warp] = acc;
    __syncthreads();
    if (threadIdx.x == 0)
        s_prefix = wred[0] + wred[1] + wred[2] + wred[3];
    __syncthreads();

    // local chunk: 1 bin per thread
    int bin = NB - 1 - (ch * LBINS + (int)threadIdx.x);
    u64 h = g_hist[gbase + bin];
    u32 pos = (u32)(h >> 47);
    u32 neg = (u32)(h >> 30) & 0x1FFFFu;
    u32 tot = pos + neg;
    u32 fx  = (u32)(h & 0x3FFFFFFFull);
    u64 item = ((u64)pos << 32) | (u64)tot;

    u64 excl;
    Scan(ts).ExclusiveSum(item, excl);

    u64 run = s_prefix + excl;
    float loss = 0.f;
    if (tot) {
        float cA = (float)(u32)(run >> 32);
        float kA = (float)(u32)(run & 0xFFFFFFFFull);
        float cB = cA + (float)pos;
        float kB = kA + (float)tot;
        float JA = 1.0f - (gts - cA) / (gts + kA - cA);
        float JB = 1.0f - (gts - cB) / (gts + kB - cB);
        float err_rep = (float)fx / (FXS * (float)tot);
        loss = err_rep * (JB - JA);
    }

    __shared__ float red[LTH];
    red[threadIdx.x] = loss;
    __syncthreads();
    for (int s = LTH / 2; s > 0; s >>= 1) {
        if (threadIdx.x < s) red[threadIdx.x] += red[threadIdx.x + s];
        __syncthreads();
    }

    __shared__ bool is_last;
    if (threadIdx.x == 0) {
        g_losspart[blockIdx.x] = red[0];
        __threadfence();
        int done = atomicAdd(&g_done, 1);
        is_last = (done == BN * LCH - 1);
    }
    __syncthreads();
    if (is_last && threadIdx.x == 0) {
        __threadfence();
        float s = 0.f;
        for (int i = 0; i < BN * LCH; i++) s += g_losspart[i];
        out[0] = s / (float)BN;
        g_done = 0;                    // reset for next graph replay
    }
}

extern "C" void kernel_launch(void* const* d_in, const int* in_sizes, int n_in,
                              void* d_out, int out_size) {
    const float* f1 = (const float*)d_in[0];
    const float* f2 = (const float*)d_in[1];
    const int*   gt = (const int*)d_in[2];
    float* out = (float*)d_out;

    void* hs = nullptr;
    cudaGetSymbolAddress(&hs, g_hist);
    cudaMemsetAsync(hs, 0, sizeof(u64) * BN * NB);

    constexpr int SSMEM = Eq * CPIX * 4;                  // 81920
    cudaFuncSetAttribute(k_stats, cudaFuncAttributeMaxDynamicSharedMemorySize, SSMEM);
    k_stats<<<STB, 256, SSMEM>>>(f1, f2, gt);

    k_stats2<<<BN, 64>>>();

    constexpr int ESMEM = Nq * NB * 8 + Eq * CPIX * 4;    // 98304 + 81920 = 180224
    cudaFuncSetAttribute(k_errhist, cudaFuncAttributeMaxDynamicSharedMemorySize, ESMEM);
    k_errhist<<<STB, 256, ESMEM>>>(f1, f2, gt);

    k_losshist<<<BN * LCH, LTH>>>(out);
}

// round 7
// speedup vs baseline: 1.2750x; 1.2750x over previous
#include <cuda_runtime.h>
#include <cuda_bf16.h>
#include <cub/cub.cuh>
#include <cstdint>

typedef unsigned int u32;
typedef unsigned long long u64;

// Problem constants
constexpr int Bq = 2, Eq = 16, Hq = 160, Wq = 288, Nq = 12, Tq = 2;
constexpr int HW  = Hq * Wq;            // 46080
constexpr int P   = Tq * HW;            // 92160 pixels per instance
constexpr int BN  = Bq * Nq;            // 24 instances

constexpr int CH   = 36;                // chunks per (b,t)
constexpr int CPIX = 1280;              // pixels per chunk (HW = 36*1280)
constexpr int NBLK = Bq * Tq * CH;      // 144 blocks
constexpr int NCHK = Tq * CH;           // 72 partial chunks per instance
constexpr int ITER = CPIX / 32;         // 40 warp iterations

constexpr int NB  = 1024;               // histogram bins over err in [0,2]
constexpr float FXS = 4096.0f;          // fixed-point scale 2^12
// hist packing: (pos<<47) | (neg<<30) | fxsum
//   pos,neg <= 92160 < 2^17; fxsum <= 92160*2*4096 = 7.6e8 < 2^30

// -------- scratch (static device globals; no runtime allocation) --------
__device__ float g_part[BN * NCHK * 33];
__device__ float g_w2[BN * Eq];         // var
__device__ float g_w1[BN * Eq];         // -2*var*mean
__device__ float g_c[BN];               // sum var*mean^2
__device__ float g_cnt[BN];
__device__ u64 g_hist[BN * NB];
__device__ float g_losspart[BN];
__device__ int g_done = 0;

// -------- kernel 1: stats, warp-per-instance, L1-reuse of feat window -----
__global__ void __launch_bounds__(384) k_stats(
    const float* __restrict__ f1, const float* __restrict__ f2,
    const int* __restrict__ gt) {
    int blk = blockIdx.x;
    int b = blk / (Tq * CH);
    int r = blk % (Tq * CH);
    int t = r / CH, ch = r % CH;
    int hw0 = ch * CPIX;
    const float* fb = (t ? f2 : f1) + (size_t)b * Eq * HW + hw0;

    int w = threadIdx.x >> 5, lane = threadIdx.x & 31;   // w = instance 0..11
    int bn = b * Nq + w;
    const int* gtp = gt + ((size_t)bn * Tq + t) * HW + hw0;

    float a[33];
#pragma unroll
    for (int q = 0; q < 33; q++) a[q] = 0.f;

    for (int it = 0; it < ITER; it++) {
        int i = it * 32 + lane;
        float m = (float)gtp[i];
        a[32] += m;
#pragma unroll
        for (int e = 0; e < Eq; e++) {
            float v = fb[(size_t)e * HW + i];
            float mv = m * v;
            a[e] += mv;
            a[16 + e] = fmaf(mv, v, a[16 + e]);
        }
    }

#pragma unroll
    for (int q = 0; q < 33; q++)
#pragma unroll
        for (int off = 16; off > 0; off >>= 1)
            a[q] += __shfl_down_sync(0xFFFFFFFFu, a[q], off);

    if (lane == 0) {
        float* dst = &g_part[((size_t)bn * NCHK + (t * CH + ch)) * 33];
#pragma unroll
        for (int q = 0; q < 33; q++) dst[q] = a[q];
    }
}

// -------- kernel 2: finalize -> w2 (var), w1 (-2*var*mean), c, cnt --------
__global__ void k_stats2() {
    int bn = blockIdx.x;
    __shared__ float sums[33];
    __shared__ float vm2[16];
    int tid = threadIdx.x;
    if (tid < 33) {
        float s = 0.f;
        for (int c = 0; c < NCHK; c++)
            s += g_part[((size_t)bn * NCHK + c) * 33 + tid];
        sums[tid] = s;
    }
    __syncthreads();
    float cnt = sums[32];
    if (tid < Eq) {
        float mean = sums[tid] / cnt;
        float var  = (sums[16 + tid] - cnt * mean * mean) / (cnt - 1.0f);
        g_w2[bn * Eq + tid] = var;
        g_w1[bn * Eq + tid] = -2.0f * var * mean;
        vm2[tid] = var * mean * mean;
    }
    __syncthreads();
    if (tid == 0) {
        float c = 0.f;
#pragma unroll
        for (int e = 0; e < Eq; e++) c += vm2[e];
        g_c[bn] = c;
        g_cnt[bn] = cnt;
    }
}

// -------- kernel 3: fused error + histogram, warp-per-instance ------------
// edge bins (err saturated at 0 or 2, ~60% of pixels) accumulate in
// registers; mid bins go straight to the global per-instance hist (u64 L2
// atomics, spread addresses, deterministic).
__global__ void __launch_bounds__(384) k_errhist(
    const float* __restrict__ f1, const float* __restrict__ f2,
    const int* __restrict__ gt) {
    int blk = blockIdx.x;
    int b = blk / (Tq * CH);
    int r = blk % (Tq * CH);
    int t = r / CH, ch = r % CH;
    int hw0 = ch * CPIX;
    const float* fb = (t ? f2 : f1) + (size_t)b * Eq * HW + hw0;

    int w = threadIdx.x >> 5, lane = threadIdx.x & 31;   // instance w
    int bn = b * Nq + w;
    const int* gtp = gt + ((size_t)bn * Tq + t) * HW + hw0;
    size_t gb = (size_t)bn * NB;

    float w2[Eq], w1[Eq];
#pragma unroll
    for (int e = 0; e < Eq; e++) {
        w2[e] = g_w2[bn * Eq + e];
        w1[e] = g_w1[bn * Eq + e];
    }
    float cc = g_c[bn];

    u32 c0 = 0, cM = 0, s0 = 0, sM = 0;    // edge bins: (pos<<16|neg), fx sums

    for (int it = 0; it < ITER; it++) {
        int i = it * 32 + lane;
        int m = gtp[i];
        float d = cc;
#pragma unroll
        for (int e = 0; e < Eq; e++) {
            float v = fb[(size_t)e * HW + i];
            d = fmaf(v, fmaf(v, w2[e], w1[e]), d);
        }
        float logit = 2.0f * __expf(-0.5f * d) - 1.0f;
        float err = m ? (1.0f - logit) : (1.0f + logit);
        u32 fx = (u32)(err * FXS + 0.5f);
        int bin = (int)(err * (0.5f * NB));
        if (bin > NB - 1) bin = NB - 1;
        u32 pc = m ? 0x10000u : 1u;
        if (bin == 0)           { c0 += pc; s0 += fx; }
        else if (bin == NB - 1) { cM += pc; sM += fx; }
        else {
            u64 add = (m ? (1ull << 47) : (1ull << 30)) | (u64)fx;
            atomicAdd(&g_hist[gb + bin], add);
        }
    }

    // warp-reduce edge accumulators, flush once per warp
#pragma unroll
    for (int off = 16; off > 0; off >>= 1) {
        c0 += __shfl_down_sync(0xFFFFFFFFu, c0, off);
        cM += __shfl_down_sync(0xFFFFFFFFu, cM, off);
        s0 += __shfl_down_sync(0xFFFFFFFFu, s0, off);
        sM += __shfl_down_sync(0xFFFFFFFFu, sM, off);
    }
    if (lane == 0) {
        if (c0)
            atomicAdd(&g_hist[gb + 0],
                ((u64)(c0 >> 16) << 47) | ((u64)(c0 & 0xFFFFu) << 30) | (u64)s0);
        if (cM)
            atomicAdd(&g_hist[gb + NB - 1],
                ((u64)(cM >> 16) << 47) | ((u64)(cM & 0xFFFFu) << 30) | (u64)sM);
    }
}

// -------- kernel 4: Lovász scan, one block per instance, fused reduce -----
__global__ void __launch_bounds__(NB) k_losshist(float* __restrict__ out) {
    int bn = blockIdx.x;
    float gts = g_cnt[bn];
    int tid = threadIdx.x;

    // descending position tid -> bin NB-1-tid
    u64 h = g_hist[(size_t)bn * NB + (NB - 1 - tid)];
    u32 pos = (u32)(h >> 47);
    u32 neg = (u32)(h >> 30) & 0x1FFFFu;
    u32 tot = pos + neg;
    u32 fx  = (u32)(h & 0x3FFFFFFFull);

    typedef cub::BlockScan<u64, NB> Scan;
    __shared__ typename Scan::TempStorage ts;
    u64 excl;
    Scan(ts).ExclusiveSum(((u64)pos << 32) | (u64)tot, excl);

    float loss = 0.f;
    if (tot) {
        float cA = (float)(u32)(excl >> 32);
        float kA = (float)(u32)(excl & 0xFFFFFFFFull);
        float cB = cA + (float)pos;
        float kB = kA + (float)tot;
        float JA = 1.0f - (gts - cA) / (gts + kA - cA);
        float JB = 1.0f - (gts - cB) / (gts + kB - cB);
        float err_rep = (float)fx / (FXS * (float)tot);
        loss = err_rep * (JB - JA);
    }

    __shared__ float red[NB];
    __syncthreads();                    // reuse of smem region timing safety
    red[tid] = loss;
    __syncthreads();
    for (int s = NB / 2; s > 0; s >>= 1) {
        if (tid < s) red[tid] += red[tid + s];
        __syncthreads();
    }

    __shared__ bool is_last;
    if (tid == 0) {
        g_losspart[bn] = red[0];
        __threadfence();
        int done = atomicAdd(&g_done, 1);
        is_last = (done == BN - 1);
    }
    __syncthreads();
    if (is_last && tid == 0) {
        __threadfence();
        float s = 0.f;
#pragma unroll
        for (int i = 0; i < BN; i++) s += g_losspart[i];
        out[0] = s / (float)BN;
        g_done = 0;                     // reset for next graph replay
    }
}

extern "C" void kernel_launch(void* const* d_in, const int* in_sizes, int n_in,
                              void* d_out, int out_size) {
    const float* f1 = (const float*)d_in[0];
    const float* f2 = (const float*)d_in[1];
    const int*   gt = (const int*)d_in[2];
    float* out = (float*)d_out;

    void* hs = nullptr;
    cudaGetSymbolAddress(&hs, g_hist);
    cudaMemsetAsync(hs, 0, sizeof(u64) * BN * NB);

    k_stats<<<NBLK, 384>>>(f1, f2, gt);
    k_stats2<<<BN, 64>>>();
    k_errhist<<<NBLK, 384>>>(f1, f2, gt);
    k_losshist<<<BN, NB>>>(out);
}

// round 8
// speedup vs baseline: 1.7485x; 1.3714x over previous
#include <cuda_runtime.h>
#include <cuda_bf16.h>
#include <cub/cub.cuh>
#include <cstdint>

typedef unsigned int u32;
typedef unsigned long long u64;

// Problem constants
constexpr int Bq = 2, Eq = 16, Hq = 160, Wq = 288, Nq = 12, Tq = 2;
constexpr int HW  = Hq * Wq;            // 46080
constexpr int P   = Tq * HW;            // 92160 pixels per instance
constexpr int BN  = Bq * Nq;            // 24 instances

constexpr int CH   = 36;                // chunks per (b,t)
constexpr int CPIX = 1280;              // pixels per chunk (HW = 36*1280)
constexpr int NBLK = Bq * Tq * CH;      // 144 blocks
constexpr int NCHK = Tq * CH;           // 72 partial chunks per instance
constexpr int ITER4 = CPIX / 128;       // 10 iters (32 lanes x 4 px)

constexpr int NB  = 1024;               // histogram bins over err in [0,2]
constexpr float FXS = 4096.0f;          // fixed-point scale 2^12
// hist packing: (pos<<47) | (neg<<30) | fxsum
//   pos,neg <= 92160 < 2^17; fxsum <= 92160*2*4096 = 7.6e8 < 2^30

constexpr int LTH = 256;                // losshist threads
constexpr int LIT = NB / LTH;           // 4 bins per thread

// -------- scratch (static device globals; no runtime allocation) --------
__device__ float g_part[BN * NCHK * 33];
__device__ float g_w2[BN * Eq];         // var
__device__ float g_w1[BN * Eq];         // -2*var*mean
__device__ float g_c[BN];               // sum var*mean^2
__device__ float g_cnt[BN];
__device__ u64 g_hist[BN * NB];
__device__ float g_losspart[BN];
__device__ int g_done_s = 0;            // stats finalize counter
__device__ int g_done_l = 0;            // loss finalize counter

// -------- kernel 1: stats, warp-per-instance, float4 loads + finalize -----
__global__ void __launch_bounds__(384) k_stats(
    const float* __restrict__ f1, const float* __restrict__ f2,
    const int* __restrict__ gt) {
    int blk = blockIdx.x;
    int b = blk / (Tq * CH);
    int r = blk % (Tq * CH);
    int t = r / CH, ch = r % CH;
    int hw0 = ch * CPIX;
    const float* fb = (t ? f2 : f1) + (size_t)b * Eq * HW + hw0;

    int w = threadIdx.x >> 5, lane = threadIdx.x & 31;   // w = instance 0..11
    int bn = b * Nq + w;
    const int4* gt4 = (const int4*)(gt + ((size_t)bn * Tq + t) * HW + hw0);

    float a[33];
#pragma unroll
    for (int q = 0; q < 33; q++) a[q] = 0.f;

    for (int it = 0; it < ITER4; it++) {
        int i4 = it * 32 + lane;
        int4 mm = gt4[i4];
        float m0 = (float)mm.x, m1 = (float)mm.y, m2 = (float)mm.z, m3 = (float)mm.w;
        a[32] += m0 + m1 + m2 + m3;
#pragma unroll
        for (int e = 0; e < Eq; e++) {
            float4 v = ((const float4*)(fb + (size_t)e * HW))[i4];
            float x0 = mm.x ? v.x : 0.f;
            float x1 = mm.y ? v.y : 0.f;
            float x2 = mm.z ? v.z : 0.f;
            float x3 = mm.w ? v.w : 0.f;
            a[e] += (x0 + x1) + (x2 + x3);
            float s2 = fmaf(x0, v.x, fmaf(x1, v.y, fmaf(x2, v.z, x3 * v.w)));
            a[16 + e] += s2;
        }
    }

#pragma unroll
    for (int q = 0; q < 33; q++)
#pragma unroll
        for (int off = 16; off > 0; off >>= 1)
            a[q] += __shfl_down_sync(0xFFFFFFFFu, a[q], off);

    if (lane == 0) {
        float* dst = &g_part[((size_t)bn * NCHK + (t * CH + ch)) * 33];
#pragma unroll
        for (int q = 0; q < 33; q++) dst[q] = a[q];
    }

    // ---- last block finalizes mean/var for all 24 instances ----
    __shared__ bool last;
    __threadfence();
    __syncthreads();
    if (threadIdx.x == 0) {
        int d = atomicAdd(&g_done_s, 1);
        last = (d == NBLK - 1);
    }
    __syncthreads();
    if (!last) return;
    __threadfence();

    __shared__ float sums[BN][33];
    __shared__ float vm2[BN][Eq];
    for (int k = threadIdx.x; k < BN * 33; k += 384) {
        int ibn = k / 33, q = k - ibn * 33;
        float s = 0.f;
        for (int c = 0; c < NCHK; c++)
            s += g_part[((size_t)ibn * NCHK + c) * 33 + q];
        sums[ibn][q] = s;
    }
    __syncthreads();
    if (threadIdx.x < BN * Eq) {
        int ibn = threadIdx.x / Eq, e = threadIdx.x % Eq;
        float cnt = sums[ibn][32];
        float mean = sums[ibn][e] / cnt;
        float var  = (sums[ibn][16 + e] - cnt * mean * mean) / (cnt - 1.0f);
        g_w2[ibn * Eq + e] = var;
        g_w1[ibn * Eq + e] = -2.0f * var * mean;
        vm2[ibn][e] = var * mean * mean;
    }
    __syncthreads();
    if (threadIdx.x < BN) {
        float c = 0.f;
#pragma unroll
        for (int e = 0; e < Eq; e++) c += vm2[threadIdx.x][e];
        g_c[threadIdx.x] = c;
        g_cnt[threadIdx.x] = sums[threadIdx.x][32];
        if (threadIdx.x == 0) g_done_s = 0;    // reset for next replay
    }
}

// -------- kernel 2: fused error + histogram, warp-per-instance, float4 ----
__global__ void __launch_bounds__(384) k_errhist(
    const float* __restrict__ f1, const float* __restrict__ f2,
    const int* __restrict__ gt) {
    int blk = blockIdx.x;
    int b = blk / (Tq * CH);
    int r = blk % (Tq * CH);
    int t = r / CH, ch = r % CH;
    int hw0 = ch * CPIX;
    const float* fb = (t ? f2 : f1) + (size_t)b * Eq * HW + hw0;

    int w = threadIdx.x >> 5, lane = threadIdx.x & 31;   // instance w
    int bn = b * Nq + w;
    const int4* gt4 = (const int4*)(gt + ((size_t)bn * Tq + t) * HW + hw0);
    size_t gb = (size_t)bn * NB;

    float w2[Eq], w1[Eq];
#pragma unroll
    for (int e = 0; e < Eq; e++) {
        w2[e] = g_w2[bn * Eq + e];
        w1[e] = g_w1[bn * Eq + e];
    }
    float cc = g_c[bn];

    u32 c0 = 0, cM = 0, s0 = 0, sM = 0;    // edge bins: (pos<<16|neg), fx sums

    for (int it = 0; it < ITER4; it++) {
        int i4 = it * 32 + lane;
        int4 mm = gt4[i4];
        float d0 = cc, d1 = cc, d2 = cc, d3 = cc;
#pragma unroll
        for (int e = 0; e < Eq; e++) {
            float4 v = ((const float4*)(fb + (size_t)e * HW))[i4];
            d0 = fmaf(v.x, fmaf(v.x, w2[e], w1[e]), d0);
            d1 = fmaf(v.y, fmaf(v.y, w2[e], w1[e]), d1);
            d2 = fmaf(v.z, fmaf(v.z, w2[e], w1[e]), d2);
            d3 = fmaf(v.w, fmaf(v.w, w2[e], w1[e]), d3);
        }
        float dd[4] = {d0, d1, d2, d3};
        int msk[4] = {mm.x, mm.y, mm.z, mm.w};
#pragma unroll
        for (int j = 0; j < 4; j++) {
            float logit = 2.0f * __expf(-0.5f * dd[j]) - 1.0f;
            float err = msk[j] ? (1.0f - logit) : (1.0f + logit);
            u32 fx = (u32)(err * FXS + 0.5f);
            int bin = (int)(err * (0.5f * NB));
            if (bin > NB - 1) bin = NB - 1;
            u32 pc = msk[j] ? 0x10000u : 1u;
            if (bin == 0)           { c0 += pc; s0 += fx; }
            else if (bin == NB - 1) { cM += pc; sM += fx; }
            else {
                u64 add = (msk[j] ? (1ull << 47) : (1ull << 30)) | (u64)fx;
                atomicAdd(&g_hist[gb + bin], add);
            }
        }
    }

    // warp-reduce edge accumulators, flush once per warp
#pragma unroll
    for (int off = 16; off > 0; off >>= 1) {
        c0 += __shfl_down_sync(0xFFFFFFFFu, c0, off);
        cM += __shfl_down_sync(0xFFFFFFFFu, cM, off);
        s0 += __shfl_down_sync(0xFFFFFFFFu, s0, off);
        sM += __shfl_down_sync(0xFFFFFFFFu, sM, off);
    }
    if (lane == 0) {
        if (c0)
            atomicAdd(&g_hist[gb + 0],
                ((u64)(c0 >> 16) << 47) | ((u64)(c0 & 0xFFFFu) << 30) | (u64)s0);
        if (cM)
            atomicAdd(&g_hist[gb + NB - 1],
                ((u64)(cM >> 16) << 47) | ((u64)(cM & 0xFFFFu) << 30) | (u64)sM);
    }
}

// -------- kernel 3: Lovász scan, block per instance, fused final ----------
__global__ void __launch_bounds__(LTH) k_losshist(float* __restrict__ out) {
    int bn = blockIdx.x;
    float gts = g_cnt[bn];
    int tid = threadIdx.x;
    size_t gbase = (size_t)bn * NB;

    // thread handles descending positions tid*LIT .. tid*LIT+LIT-1
    u32 pos[LIT], tot[LIT], fx[LIT];
    u64 tsum = 0ull;
#pragma unroll
    for (int i = 0; i < LIT; i++) {
        int bin = NB - 1 - (tid * LIT + i);
        u64 h = g_hist[gbase + bin];
        pos[i] = (u32)(h >> 47);
        u32 neg = (u32)(h >> 30) & 0x1FFFFu;
        tot[i] = pos[i] + neg;
        fx[i]  = (u32)(h & 0x3FFFFFFFull);
        tsum += ((u64)pos[i] << 32) | (u64)tot[i];
    }

    typedef cub::BlockScan<u64, LTH> Scan;
    __shared__ typename Scan::TempStorage ts;
    u64 excl;
    Scan(ts).ExclusiveSum(tsum, excl);

    u64 run = excl;
    float loss = 0.f;
#pragma unroll
    for (int i = 0; i < LIT; i++) {
        if (tot[i]) {
            float cA = (float)(u32)(run >> 32);
            float kA = (float)(u32)(run & 0xFFFFFFFFull);
            float cB = cA + (float)pos[i];
            float kB = kA + (float)tot[i];
            float JA = 1.0f - (gts - cA) / (gts + kA - cA);
            float JB = 1.0f - (gts - cB) / (gts + kB - cB);
            float err_rep = (float)fx[i] / (FXS * (float)tot[i]);
            loss += err_rep * (JB - JA);
        }
        run += ((u64)pos[i] << 32) | (u64)tot[i];
    }

    __shared__ float red[LTH];
    __syncthreads();
    red[tid] = loss;
    __syncthreads();
    for (int s = LTH / 2; s > 0; s >>= 1) {
        if (tid < s) red[tid] += red[tid + s];
        __syncthreads();
    }

    __shared__ bool is_last;
    if (tid == 0) {
        g_losspart[bn] = red[0];
        __threadfence();
        int done = atomicAdd(&g_done_l, 1);
        is_last = (done == BN - 1);
    }
    __syncthreads();
    if (is_last && tid == 0) {
        __threadfence();
        float s = 0.f;
#pragma unroll
        for (int i = 0; i < BN; i++) s += g_losspart[i];
        out[0] = s / (float)BN;
        g_done_l = 0;                   // reset for next graph replay
    }
}

extern "C" void kernel_launch(void* const* d_in, const int* in_sizes, int n_in,
                              void* d_out, int out_size) {
    const float* f1 = (const float*)d_in[0];
    const float* f2 = (const float*)d_in[1];
    const int*   gt = (const int*)d_in[2];
    float* out = (float*)d_out;

    void* hs = nullptr;
    cudaGetSymbolAddress(&hs, g_hist);
    cudaMemsetAsync(hs, 0, sizeof(u64) * BN * NB);

    k_stats<<<NBLK, 384>>>(f1, f2, gt);
    k_errhist<<<NBLK, 384>>>(f1, f2, gt);
    k_losshist<<<BN, LTH>>>(out);
}